// round 14
// baseline (speedup 1.0000x reference)
#include <cuda_runtime.h>
#include <cstdint>

#define D_MODEL 1024
#define NHEAD 16
#define DEPTH 64
#define BB 2
#define SEQ 2048
#define MTOT (BB * SEQ)  // 4096

// Scratch (allocation-free rule: __device__ globals)
__device__ float g_qh[(size_t)BB * NHEAD * SEQ * DEPTH];  // [B,H,S,64]  (tf32-rounded)
__device__ float g_kh[(size_t)BB * NHEAD * DEPTH * SEQ];  // [B,H,64,S]  TRANSPOSED (tf32-rounded)
__device__ float g_vh[(size_t)BB * NHEAD * SEQ * DEPTH];  // [B,H,S,64]  (tf32-rounded)
__device__ float g_att[(size_t)MTOT * D_MODEL];           // [B,S,1024] merged heads

__device__ __forceinline__ uint32_t f2tf(float f) {
    uint32_t u;
    asm("cvt.rna.tf32.f32 %0, %1;" : "=r"(u) : "f"(f));
    return u;
}

__device__ __forceinline__ void mma_tf32(float& c0, float& c1, float& c2, float& c3,
                                         uint32_t a0, uint32_t a1, uint32_t a2, uint32_t a3,
                                         uint32_t b0, uint32_t b1) {
    asm("mma.sync.aligned.m16n8k8.row.col.f32.tf32.tf32.f32 "
        "{%0,%1,%2,%3},{%4,%5,%6,%7},{%8,%9},{%0,%1,%2,%3};"
        : "+f"(c0), "+f"(c1), "+f"(c2), "+f"(c3)
        : "r"(a0), "r"(a1), "r"(a2), "r"(a3), "r"(b0), "r"(b1));
}

__device__ __forceinline__ uint32_t s2u(const void* p) {
    return (uint32_t)__cvta_generic_to_shared(p);
}
#define CP16(dst_u32, src_ptr) \
    asm volatile("cp.async.ca.shared.global [%0], [%1], 16;" :: "r"(dst_u32), "l"(src_ptr) : "memory")
#define CPCOMMIT() asm volatile("cp.async.commit_group;" ::: "memory")
#define CPWAIT1()  asm volatile("cp.async.wait_group 1;" ::: "memory")

// ===========================================================================
// tf32 tensor-core GEMM: Y = X @ W + bias.  M=4096, N=K=1024.
// MODE 0: plain row-major [M,N] fp32 out (final output)
// MODE 1: head-split [B,H,S,64], tf32-pre-rounded (Q, V)
// MODE 2: head-split TRANSPOSED [B,H,64,S], tf32-pre-rounded (K)
// ===========================================================================
#define BKK 32
#define ASTR 36
#define BSTR 136
#define PERBUF (128 * ASTR + BKK * BSTR)
#define GEMM_SMEM (2 * PERBUF * 4)

template <int MODE>
__device__ __forceinline__ void gemm_tf32_body(
    const float* __restrict__ X, const float* __restrict__ W,
    const float* __restrict__ bias, float* __restrict__ Y)
{
    extern __shared__ uint32_t smu[];

    const int K = D_MODEL, N = D_MODEL;
    const int m0 = blockIdx.y * 128;
    const int n0 = blockIdx.x * 128;
    const int tid = threadIdx.x;
    const int lane = tid & 31;
    const int wid = tid >> 5;
    const int warpM = wid >> 2;
    const int warpN = wid & 3;
    const int g = lane >> 2;
    const int t = lane & 3;

    const float* xp = X + (size_t)(m0 + (tid >> 3)) * K + (tid & 7) * 4;
    const float* wp = W + (size_t)(tid >> 5) * N + n0 + (tid & 31) * 4;

    const int aOff = (tid >> 3) * ASTR + (tid & 7) * 4;
    const int bOff = (tid >> 5) * BSTR + (tid & 31) * 4;

    float acc[4][4][4];
#pragma unroll
    for (int mt = 0; mt < 4; ++mt)
#pragma unroll
        for (int nt = 0; nt < 4; ++nt)
#pragma unroll
            for (int r = 0; r < 4; ++r) acc[mt][nt][r] = 0.f;

    float4 ra[4], rb[4];

#pragma unroll
    for (int i = 0; i < 4; ++i) {
        ra[i] = *(const float4*)(xp + (size_t)i * 32 * K);
        rb[i] = *(const float4*)(wp + (size_t)i * 8 * N);
    }
    {
        uint32_t* Au = smu;
        uint32_t* Bu = smu + 128 * ASTR;
#pragma unroll
        for (int i = 0; i < 4; ++i) {
            uint32_t* ap = Au + aOff + i * 32 * ASTR;
            uint2 p0 = make_uint2(f2tf(ra[i].x), f2tf(ra[i].y));
            uint2 p1 = make_uint2(f2tf(ra[i].z), f2tf(ra[i].w));
            *(uint2*)(ap + 0) = p0;
            *(uint2*)(ap + 2) = p1;
            uint4 q = make_uint4(f2tf(rb[i].x), f2tf(rb[i].y), f2tf(rb[i].z), f2tf(rb[i].w));
            *(uint4*)(Bu + bOff + i * 8 * BSTR) = q;
        }
    }
    __syncthreads();

    const int NKT = K / BKK;
    for (int kt = 0; kt < NKT; ++kt) {
        if (kt + 1 < NKT) {
#pragma unroll
            for (int i = 0; i < 4; ++i) {
                ra[i] = *(const float4*)(xp + (kt + 1) * BKK + (size_t)i * 32 * K);
                rb[i] = *(const float4*)(wp + ((size_t)(kt + 1) * BKK + i * 8) * N);
            }
        }
        {
            const uint32_t* Au = smu + (kt & 1) * PERBUF;
            const uint32_t* Bu = Au + 128 * ASTR;
            const int mBase = warpM * 64 + g;
            const int nBase = warpN * 32 + g;
#pragma unroll
            for (int ks = 0; ks < 4; ++ks) {
                const int k0 = ks * 8;
                uint32_t af[4][4], bf[4][2];
#pragma unroll
                for (int mt = 0; mt < 4; ++mt) {
                    const uint32_t* base = Au + (mBase + mt * 16) * ASTR + k0 + t;
                    af[mt][0] = base[0];
                    af[mt][1] = base[8 * ASTR];
                    af[mt][2] = base[4];
                    af[mt][3] = base[8 * ASTR + 4];
                }
#pragma unroll
                for (int nt = 0; nt < 4; ++nt) {
                    const uint32_t* base = Bu + (k0 + t) * BSTR + nBase + nt * 8;
                    bf[nt][0] = base[0];
                    bf[nt][1] = base[4 * BSTR];
                }
#pragma unroll
                for (int mt = 0; mt < 4; ++mt)
#pragma unroll
                    for (int nt = 0; nt < 4; ++nt)
                        mma_tf32(acc[mt][nt][0], acc[mt][nt][1], acc[mt][nt][2], acc[mt][nt][3],
                                 af[mt][0], af[mt][1], af[mt][2], af[mt][3],
                                 bf[nt][0], bf[nt][1]);
            }
        }
        if (kt + 1 < NKT) {
            uint32_t* Au = smu + ((kt + 1) & 1) * PERBUF;
            uint32_t* Bu = Au + 128 * ASTR;
#pragma unroll
            for (int i = 0; i < 4; ++i) {
                uint32_t* ap = Au + aOff + i * 32 * ASTR;
                uint2 p0 = make_uint2(f2tf(ra[i].x), f2tf(ra[i].y));
                uint2 p1 = make_uint2(f2tf(ra[i].z), f2tf(ra[i].w));
                *(uint2*)(ap + 0) = p0;
                *(uint2*)(ap + 2) = p1;
                uint4 q = make_uint4(f2tf(rb[i].x), f2tf(rb[i].y), f2tf(rb[i].z), f2tf(rb[i].w));
                *(uint4*)(Bu + bOff + i * 8 * BSTR) = q;
            }
        }
        __syncthreads();
    }

#pragma unroll
    for (int mt = 0; mt < 4; ++mt) {
#pragma unroll
        for (int nt = 0; nt < 4; ++nt) {
            const int m = m0 + warpM * 64 + mt * 16 + g;
            const int n = n0 + warpN * 32 + nt * 8 + 2 * t;
            const float b0v = bias[n], b1v = bias[n + 1];
            const float v0 = acc[mt][nt][0] + b0v;
            const float v1 = acc[mt][nt][1] + b1v;
            const float v2 = acc[mt][nt][2] + b0v;
            const float v3 = acc[mt][nt][3] + b1v;
            if (MODE == 0) {
                *(float2*)&Y[(size_t)m * N + n] = make_float2(v0, v1);
                *(float2*)&Y[(size_t)(m + 8) * N + n] = make_float2(v2, v3);
            } else if (MODE == 1) {
                const int h = n >> 6;
                const int d = n & 63;
                const int bb = m >> 11;
                const int sq = m & (SEQ - 1);
                const int m2 = m + 8;
                const int bb2 = m2 >> 11;
                const int sq2 = m2 & (SEQ - 1);
                float2 lo = make_float2(__uint_as_float(f2tf(v0)), __uint_as_float(f2tf(v1)));
                float2 hi = make_float2(__uint_as_float(f2tf(v2)), __uint_as_float(f2tf(v3)));
                *(float2*)(Y + (((size_t)bb * NHEAD + h) * SEQ + sq) * DEPTH + d) = lo;
                *(float2*)(Y + (((size_t)bb2 * NHEAD + h) * SEQ + sq2) * DEPTH + d) = hi;
            } else {
                // MODE 2: K transposed [B,H,64,S]
                const int h = n >> 6;
                const int d = n & 63;
                const int bb = m >> 11;
                const int sq = m & (SEQ - 1);
                const int m2 = m + 8;
                const int bb2 = m2 >> 11;
                const int sq2 = m2 & (SEQ - 1);
                const size_t base = ((size_t)bb * NHEAD + h) * DEPTH * SEQ;
                const size_t base2 = ((size_t)bb2 * NHEAD + h) * DEPTH * SEQ;
                Y[base + (size_t)d * SEQ + sq]        = __uint_as_float(f2tf(v0));
                Y[base + (size_t)(d + 1) * SEQ + sq]  = __uint_as_float(f2tf(v1));
                Y[base2 + (size_t)d * SEQ + sq2]       = __uint_as_float(f2tf(v2));
                Y[base2 + (size_t)(d + 1) * SEQ + sq2] = __uint_as_float(f2tf(v3));
            }
        }
    }
}

__global__ __launch_bounds__(256) void qkv_proj_kernel(
    const float* __restrict__ q, const float* __restrict__ k, const float* __restrict__ v,
    const float* __restrict__ wq, const float* __restrict__ wk, const float* __restrict__ wv,
    const float* __restrict__ bq, const float* __restrict__ bk, const float* __restrict__ bv)
{
    if (blockIdx.z == 0)      gemm_tf32_body<1>(q, wq, bq, g_qh);
    else if (blockIdx.z == 1) gemm_tf32_body<2>(k, wk, bk, g_kh);
    else                      gemm_tf32_body<1>(v, wv, bv, g_vh);
}

__global__ __launch_bounds__(256) void out_proj_kernel(
    const float* __restrict__ wo, const float* __restrict__ bo, float* __restrict__ out)
{
    gemm_tf32_body<0>(g_att, wo, bo, out);
}

// ===========================================================================
// tf32 tensor-core flash attention, cp.async double-buffered.
// CTA: 128 q-rows x one (b,h). 256 threads = 8 warps; warp owns 16 q-rows
// (one m16 tile). kv-tiles of 64, 32 iterations. 4 warps/SMSP for stall cover.
// K arrives pre-transposed [d][s] and pre-rounded -> straight cp.async copy.
// P never touches smem: C-frag -> A-frag via quad shuffles.
// Smem (words): Qs 128x68 | K0 64x72 | K1 | V0 64x72 | V1 = 27136 w = 108544 B
//   -> 2 CTAs/SM, regs capped at 128 via launch_bounds(256,2).
// ===========================================================================
#define QSTR 68
#define KSTR 72
#define KVWORDS (64 * KSTR)  // 4608
#define FLASH_SMEM ((128 * QSTR + 4 * KVWORDS) * 4)   // 108544

__global__ __launch_bounds__(256, 2) void flash_attn_tf32_kernel(const float* __restrict__ mask)
{
    extern __shared__ uint32_t su[];
    uint32_t* Qs = su;                                   // [128][68]
    uint32_t* Kb0 = su + 128 * QSTR;                     // [64][72]  [d][kv]
    uint32_t* Kb1 = Kb0 + KVWORDS;
    uint32_t* Vb0 = Kb1 + KVWORDS;                       // [64][72]  [kv][d]
    uint32_t* Vb1 = Vb0 + KVWORDS;

    const int bh = blockIdx.y;               // b*16 + h
    const int q0 = blockIdx.x * 128;
    const float* Qp = g_qh + ((size_t)bh * SEQ + q0) * DEPTH;
    const float* KpT = g_kh + (size_t)bh * DEPTH * SEQ;   // transposed [64][SEQ]
    const float* Vp = g_vh + (size_t)bh * SEQ * DEPTH;

    const int tid = threadIdx.x;
    const int lane = tid & 31;
    const int wid = tid >> 5;                // 0..7
    const int g = lane >> 2;                 // 0..7
    const int t = lane & 3;                  // 0..3
    const int wbase = wid * 16;              // warp's q-row base (local)
    const int srcA = (lane & ~3) | (t >> 1); // quad-lane for P col t
    const int srcB = srcA + 2;               // quad-lane for P col t+4

    // ---- prologue: stage Q + tile0, tile1 (256 threads) ----
    {
        // Q: 128 rows x 64 cols = 2048 cp16; 8 per thread
        const int qr = tid >> 1;                  // 0..127
        const int qc = (tid & 1) * 32;            // 0 or 32
#pragma unroll
        for (int i = 0; i < 8; ++i)
            CP16(s2u(Qs + qr * QSTR + qc + i * 4), Qp + (size_t)qr * DEPTH + qc + i * 4);

        // K/V tiles: 64 rows x 16 col-chunks = 1024 cp16 each; 4 per thread each
        const int r = tid >> 2;                   // 0..63
        const int cbase = (tid & 3) * 16;         // 0,16,32,48
#pragma unroll
        for (int i = 0; i < 4; ++i) {
            CP16(s2u(Kb0 + r * KSTR + cbase + i * 4), KpT + (size_t)r * SEQ + 0 + cbase + i * 4);
            CP16(s2u(Vb0 + r * KSTR + cbase + i * 4), Vp + (size_t)(0 + r) * DEPTH + cbase + i * 4);
        }
        CPCOMMIT();
#pragma unroll
        for (int i = 0; i < 4; ++i) {
            CP16(s2u(Kb1 + r * KSTR + cbase + i * 4), KpT + (size_t)r * SEQ + 64 + cbase + i * 4);
            CP16(s2u(Vb1 + r * KSTR + cbase + i * 4), Vp + (size_t)(64 + r) * DEPTH + cbase + i * 4);
        }
        CPCOMMIT();
    }

    float m_iA = -1e30f, m_iB = -1e30f, l_iA = 0.f, l_iB = 0.f;
    float o[8][4];
#pragma unroll
    for (int nt = 0; nt < 8; ++nt)
#pragma unroll
        for (int r = 0; r < 4; ++r) o[nt][r] = 0.f;

    const float* mrowA = mask + (size_t)(q0 + wbase + g) * SEQ + 2 * t;
    const float* mrowB = mrowA + (size_t)8 * SEQ;

    const int NT = SEQ / 64;  // 32
    for (int kt = 0; kt < NT; ++kt) {
        const int k0g = kt * 64;
        CPWAIT1();
        __syncthreads();   // tile kt resident; prior readers of this buf done

        const uint32_t* Ks = (kt & 1) ? Kb1 : Kb0;
        const uint32_t* Vs = (kt & 1) ? Vb1 : Vb0;

        // ---- S = Q K^T ----
        float s[8][4];
#pragma unroll
        for (int nt = 0; nt < 8; ++nt)
#pragma unroll
            for (int r = 0; r < 4; ++r) s[nt][r] = 0.f;

#pragma unroll
        for (int ks = 0; ks < 8; ++ks) {
            const int k0 = ks * 8;
            const uint32_t* abase = Qs + (wbase + g) * QSTR + k0 + t;
            const uint32_t a0 = abase[0];
            const uint32_t a1 = abase[8 * QSTR];
            const uint32_t a2 = abase[4];
            const uint32_t a3 = abase[8 * QSTR + 4];
#pragma unroll
            for (int nt = 0; nt < 8; ++nt) {
                const uint32_t* bp = Ks + (k0 + t) * KSTR + nt * 8 + g;
                mma_tf32(s[nt][0], s[nt][1], s[nt][2], s[nt][3],
                         a0, a1, a2, a3, bp[0], bp[4 * KSTR]);
            }
        }

        // ---- online softmax (thread owns rows g / g+8, 16 cols) ----
        {
            const float scale = 0.125f;
            const float* mrA = mrowA + k0g;
            const float* mrB = mrowB + k0g;
            float mxA = -1e30f, mxB = -1e30f;
#pragma unroll
            for (int nt = 0; nt < 8; ++nt) {
                const float2 mA = *(const float2*)(mrA + nt * 8);
                const float2 mB = *(const float2*)(mrB + nt * 8);
                s[nt][0] = s[nt][0] * scale - 1e9f * mA.x;
                s[nt][1] = s[nt][1] * scale - 1e9f * mA.y;
                s[nt][2] = s[nt][2] * scale - 1e9f * mB.x;
                s[nt][3] = s[nt][3] * scale - 1e9f * mB.y;
                mxA = fmaxf(mxA, fmaxf(s[nt][0], s[nt][1]));
                mxB = fmaxf(mxB, fmaxf(s[nt][2], s[nt][3]));
            }
            mxA = fmaxf(mxA, __shfl_xor_sync(0xffffffffu, mxA, 1));
            mxA = fmaxf(mxA, __shfl_xor_sync(0xffffffffu, mxA, 2));
            mxB = fmaxf(mxB, __shfl_xor_sync(0xffffffffu, mxB, 1));
            mxB = fmaxf(mxB, __shfl_xor_sync(0xffffffffu, mxB, 2));

            const float mnA = fmaxf(m_iA, mxA);
            const float mnB = fmaxf(m_iB, mxB);
            const float corrA = __expf(m_iA - mnA);
            const float corrB = __expf(m_iB - mnB);
            m_iA = mnA;
            m_iB = mnB;

            float rsA = 0.f, rsB = 0.f;
#pragma unroll
            for (int nt = 0; nt < 8; ++nt) {
                s[nt][0] = __expf(s[nt][0] - mnA);
                s[nt][1] = __expf(s[nt][1] - mnA);
                s[nt][2] = __expf(s[nt][2] - mnB);
                s[nt][3] = __expf(s[nt][3] - mnB);
                rsA += s[nt][0] + s[nt][1];
                rsB += s[nt][2] + s[nt][3];
            }
            rsA += __shfl_xor_sync(0xffffffffu, rsA, 1);
            rsA += __shfl_xor_sync(0xffffffffu, rsA, 2);
            rsB += __shfl_xor_sync(0xffffffffu, rsB, 1);
            rsB += __shfl_xor_sync(0xffffffffu, rsB, 2);

            l_iA = l_iA * corrA + rsA;
            l_iB = l_iB * corrB + rsB;
#pragma unroll
            for (int nt = 0; nt < 8; ++nt) {
                o[nt][0] *= corrA;
                o[nt][1] *= corrA;
                o[nt][2] *= corrB;
                o[nt][3] *= corrB;
            }
        }

        // ---- O += P V.  P: C-frag -> A-frag via quad shuffles (no smem) ----
        // C-frag: thread(g,t) holds P[g][8ks+2t], P[g][8ks+2t+1], P[g+8][..], P[g+8][..]
        // A-frag needs P[g][8ks+t], P[g+8][8ks+t], P[g][8ks+t+4], P[g+8][8ks+t+4]
#pragma unroll
        for (int ks = 0; ks < 8; ++ks) {
            const int k0 = ks * 8;
            float e0, e1;
            e0 = __shfl_sync(0xffffffffu, s[ks][0], srcA);
            e1 = __shfl_sync(0xffffffffu, s[ks][1], srcA);
            const float v0 = (t & 1) ? e1 : e0;                 // P[g][k0+t]
            e0 = __shfl_sync(0xffffffffu, s[ks][2], srcA);
            e1 = __shfl_sync(0xffffffffu, s[ks][3], srcA);
            const float v1 = (t & 1) ? e1 : e0;                 // P[g+8][k0+t]
            e0 = __shfl_sync(0xffffffffu, s[ks][0], srcB);
            e1 = __shfl_sync(0xffffffffu, s[ks][1], srcB);
            const float v2 = (t & 1) ? e1 : e0;                 // P[g][k0+t+4]
            e0 = __shfl_sync(0xffffffffu, s[ks][2], srcB);
            e1 = __shfl_sync(0xffffffffu, s[ks][3], srcB);
            const float v3 = (t & 1) ? e1 : e0;                 // P[g+8][k0+t+4]
            const uint32_t a0 = f2tf(v0);
            const uint32_t a1 = f2tf(v1);
            const uint32_t a2 = f2tf(v2);
            const uint32_t a3 = f2tf(v3);
#pragma unroll
            for (int nt = 0; nt < 8; ++nt) {
                const uint32_t* bp = Vs + (k0 + t) * KSTR + nt * 8 + g;
                mma_tf32(o[nt][0], o[nt][1], o[nt][2], o[nt][3],
                         a0, a1, a2, a3, bp[0], bp[4 * KSTR]);
            }
        }

        __syncthreads();   // all warps done reading buf (kt&1) before refill

        // ---- stage tile kt+2 into buf (kt&1) ----
        if (kt + 2 < NT) {
            const int k2 = (kt + 2) * 64;
            uint32_t* Kd = (kt & 1) ? Kb1 : Kb0;
            uint32_t* Vd = (kt & 1) ? Vb1 : Vb0;
            const int r = tid >> 2;
            const int cbase = (tid & 3) * 16;
#pragma unroll
            for (int i = 0; i < 4; ++i) {
                CP16(s2u(Kd + r * KSTR + cbase + i * 4), KpT + (size_t)r * SEQ + k2 + cbase + i * 4);
                CP16(s2u(Vd + r * KSTR + cbase + i * 4), Vp + (size_t)(k2 + r) * DEPTH + cbase + i * 4);
            }
        }
        CPCOMMIT();   // always commit (possibly empty) to keep wait accounting
    }

    // ---- epilogue: normalize + write merged-head layout [B,S,1024] ----
    const int bb2 = bh >> 4;
    const int h = bh & 15;
    {
        const float invA = 1.f / l_iA;
        const float invB = 1.f / l_iB;
        const int rowA = q0 + wbase + g;
        float* oA = g_att + ((size_t)bb2 * SEQ + rowA) * D_MODEL + h * DEPTH + 2 * t;
        float* oB = oA + (size_t)8 * D_MODEL;
#pragma unroll
        for (int nt = 0; nt < 8; ++nt) {
            *(float2*)(oA + nt * 8) = make_float2(o[nt][0] * invA, o[nt][1] * invA);
            *(float2*)(oB + nt * 8) = make_float2(o[nt][2] * invB, o[nt][3] * invB);
        }
    }
}

// ---------------------------------------------------------------------------
extern "C" void kernel_launch(void* const* d_in, const int* in_sizes, int n_in,
                              void* d_out, int out_size)
{
    const float* q    = (const float*)d_in[0];
    const float* k    = (const float*)d_in[1];
    const float* v    = (const float*)d_in[2];
    const float* mask = (const float*)d_in[3];
    const float* wq   = (const float*)d_in[4];
    const float* bq   = (const float*)d_in[5];
    const float* wk   = (const float*)d_in[6];
    const float* bk   = (const float*)d_in[7];
    const float* wv   = (const float*)d_in[8];
    const float* bv   = (const float*)d_in[9];
    const float* wo   = (const float*)d_in[10];
    const float* bo   = (const float*)d_in[11];
    float* out = (float*)d_out;

    (void)in_sizes; (void)n_in; (void)out_size;

    cudaFuncSetAttribute(qkv_proj_kernel,
                         cudaFuncAttributeMaxDynamicSharedMemorySize, GEMM_SMEM);
    cudaFuncSetAttribute(out_proj_kernel,
                         cudaFuncAttributeMaxDynamicSharedMemorySize, GEMM_SMEM);
    cudaFuncSetAttribute(flash_attn_tf32_kernel,
                         cudaFuncAttributeMaxDynamicSharedMemorySize, FLASH_SMEM);

    dim3 gproj(D_MODEL / 128, MTOT / 128, 3);
    qkv_proj_kernel<<<gproj, 256, GEMM_SMEM>>>(q, k, v, wq, wk, wv, bq, bk, bv);

    flash_attn_tf32_kernel<<<dim3(SEQ / 128, BB * NHEAD), 256, FLASH_SMEM>>>(mask);

    out_proj_kernel<<<dim3(D_MODEL / 128, MTOT / 128), 256, GEMM_SMEM>>>(wo, bo, out);
}

// round 15
// speedup vs baseline: 1.2352x; 1.2352x over previous
#include <cuda_runtime.h>
#include <cstdint>

#define D_MODEL 1024
#define NHEAD 16
#define DEPTH 64
#define BB 2
#define SEQ 2048
#define MTOT (BB * SEQ)  // 4096

// Scratch (allocation-free rule: __device__ globals)
__device__ float g_qh[(size_t)BB * NHEAD * SEQ * DEPTH];  // [B,H,S,64]  (tf32-rounded)
__device__ float g_kh[(size_t)BB * NHEAD * DEPTH * SEQ];  // [B,H,64,S]  TRANSPOSED (tf32-rounded)
__device__ float g_vh[(size_t)BB * NHEAD * SEQ * DEPTH];  // [B,H,S,64]  (tf32-rounded)
__device__ float g_att[(size_t)MTOT * D_MODEL];           // [B,S,1024] merged heads

__device__ __forceinline__ uint32_t f2tf(float f) {
    uint32_t u;
    asm("cvt.rna.tf32.f32 %0, %1;" : "=r"(u) : "f"(f));
    return u;
}

__device__ __forceinline__ void mma_tf32(float& c0, float& c1, float& c2, float& c3,
                                         uint32_t a0, uint32_t a1, uint32_t a2, uint32_t a3,
                                         uint32_t b0, uint32_t b1) {
    asm("mma.sync.aligned.m16n8k8.row.col.f32.tf32.tf32.f32 "
        "{%0,%1,%2,%3},{%4,%5,%6,%7},{%8,%9},{%0,%1,%2,%3};"
        : "+f"(c0), "+f"(c1), "+f"(c2), "+f"(c3)
        : "r"(a0), "r"(a1), "r"(a2), "r"(a3), "r"(b0), "r"(b1));
}

__device__ __forceinline__ uint32_t s2u(const void* p) {
    return (uint32_t)__cvta_generic_to_shared(p);
}
#define CP16(dst_u32, src_ptr) \
    asm volatile("cp.async.ca.shared.global [%0], [%1], 16;" :: "r"(dst_u32), "l"(src_ptr) : "memory")
#define CPCOMMIT() asm volatile("cp.async.commit_group;" ::: "memory")
#define CPWAIT1()  asm volatile("cp.async.wait_group 1;" ::: "memory")

// ===========================================================================
// tf32 tensor-core GEMM: Y = X @ W + bias.  M=4096, N=K=1024.
// MODE 0: plain row-major [M,N] fp32 out (final output)
// MODE 1: head-split [B,H,S,64], tf32-pre-rounded (Q, V)
// MODE 2: head-split TRANSPOSED [B,H,64,S], tf32-pre-rounded (K)
// ===========================================================================
#define BKK 32
#define ASTR 36
#define BSTR 136
#define PERBUF (128 * ASTR + BKK * BSTR)
#define GEMM_SMEM (2 * PERBUF * 4)

template <int MODE>
__device__ __forceinline__ void gemm_tf32_body(
    const float* __restrict__ X, const float* __restrict__ W,
    const float* __restrict__ bias, float* __restrict__ Y)
{
    extern __shared__ uint32_t smu[];

    const int K = D_MODEL, N = D_MODEL;
    const int m0 = blockIdx.y * 128;
    const int n0 = blockIdx.x * 128;
    const int tid = threadIdx.x;
    const int lane = tid & 31;
    const int wid = tid >> 5;
    const int warpM = wid >> 2;
    const int warpN = wid & 3;
    const int g = lane >> 2;
    const int t = lane & 3;

    const float* xp = X + (size_t)(m0 + (tid >> 3)) * K + (tid & 7) * 4;
    const float* wp = W + (size_t)(tid >> 5) * N + n0 + (tid & 31) * 4;

    const int aOff = (tid >> 3) * ASTR + (tid & 7) * 4;
    const int bOff = (tid >> 5) * BSTR + (tid & 31) * 4;

    float acc[4][4][4];
#pragma unroll
    for (int mt = 0; mt < 4; ++mt)
#pragma unroll
        for (int nt = 0; nt < 4; ++nt)
#pragma unroll
            for (int r = 0; r < 4; ++r) acc[mt][nt][r] = 0.f;

    float4 ra[4], rb[4];

#pragma unroll
    for (int i = 0; i < 4; ++i) {
        ra[i] = *(const float4*)(xp + (size_t)i * 32 * K);
        rb[i] = *(const float4*)(wp + (size_t)i * 8 * N);
    }
    {
        uint32_t* Au = smu;
        uint32_t* Bu = smu + 128 * ASTR;
#pragma unroll
        for (int i = 0; i < 4; ++i) {
            uint32_t* ap = Au + aOff + i * 32 * ASTR;
            uint2 p0 = make_uint2(f2tf(ra[i].x), f2tf(ra[i].y));
            uint2 p1 = make_uint2(f2tf(ra[i].z), f2tf(ra[i].w));
            *(uint2*)(ap + 0) = p0;
            *(uint2*)(ap + 2) = p1;
            uint4 q = make_uint4(f2tf(rb[i].x), f2tf(rb[i].y), f2tf(rb[i].z), f2tf(rb[i].w));
            *(uint4*)(Bu + bOff + i * 8 * BSTR) = q;
        }
    }
    __syncthreads();

    const int NKT = K / BKK;
    for (int kt = 0; kt < NKT; ++kt) {
        if (kt + 1 < NKT) {
#pragma unroll
            for (int i = 0; i < 4; ++i) {
                ra[i] = *(const float4*)(xp + (kt + 1) * BKK + (size_t)i * 32 * K);
                rb[i] = *(const float4*)(wp + ((size_t)(kt + 1) * BKK + i * 8) * N);
            }
        }
        {
            const uint32_t* Au = smu + (kt & 1) * PERBUF;
            const uint32_t* Bu = Au + 128 * ASTR;
            const int mBase = warpM * 64 + g;
            const int nBase = warpN * 32 + g;
#pragma unroll
            for (int ks = 0; ks < 4; ++ks) {
                const int k0 = ks * 8;
                uint32_t af[4][4], bf[4][2];
#pragma unroll
                for (int mt = 0; mt < 4; ++mt) {
                    const uint32_t* base = Au + (mBase + mt * 16) * ASTR + k0 + t;
                    af[mt][0] = base[0];
                    af[mt][1] = base[8 * ASTR];
                    af[mt][2] = base[4];
                    af[mt][3] = base[8 * ASTR + 4];
                }
#pragma unroll
                for (int nt = 0; nt < 4; ++nt) {
                    const uint32_t* base = Bu + (k0 + t) * BSTR + nBase + nt * 8;
                    bf[nt][0] = base[0];
                    bf[nt][1] = base[4 * BSTR];
                }
#pragma unroll
                for (int mt = 0; mt < 4; ++mt)
#pragma unroll
                    for (int nt = 0; nt < 4; ++nt)
                        mma_tf32(acc[mt][nt][0], acc[mt][nt][1], acc[mt][nt][2], acc[mt][nt][3],
                                 af[mt][0], af[mt][1], af[mt][2], af[mt][3],
                                 bf[nt][0], bf[nt][1]);
            }
        }
        if (kt + 1 < NKT) {
            uint32_t* Au = smu + ((kt + 1) & 1) * PERBUF;
            uint32_t* Bu = Au + 128 * ASTR;
#pragma unroll
            for (int i = 0; i < 4; ++i) {
                uint32_t* ap = Au + aOff + i * 32 * ASTR;
                uint2 p0 = make_uint2(f2tf(ra[i].x), f2tf(ra[i].y));
                uint2 p1 = make_uint2(f2tf(ra[i].z), f2tf(ra[i].w));
                *(uint2*)(ap + 0) = p0;
                *(uint2*)(ap + 2) = p1;
                uint4 q = make_uint4(f2tf(rb[i].x), f2tf(rb[i].y), f2tf(rb[i].z), f2tf(rb[i].w));
                *(uint4*)(Bu + bOff + i * 8 * BSTR) = q;
            }
        }
        __syncthreads();
    }

#pragma unroll
    for (int mt = 0; mt < 4; ++mt) {
#pragma unroll
        for (int nt = 0; nt < 4; ++nt) {
            const int m = m0 + warpM * 64 + mt * 16 + g;
            const int n = n0 + warpN * 32 + nt * 8 + 2 * t;
            const float b0v = bias[n], b1v = bias[n + 1];
            const float v0 = acc[mt][nt][0] + b0v;
            const float v1 = acc[mt][nt][1] + b1v;
            const float v2 = acc[mt][nt][2] + b0v;
            const float v3 = acc[mt][nt][3] + b1v;
            if (MODE == 0) {
                *(float2*)&Y[(size_t)m * N + n] = make_float2(v0, v1);
                *(float2*)&Y[(size_t)(m + 8) * N + n] = make_float2(v2, v3);
            } else if (MODE == 1) {
                const int h = n >> 6;
                const int d = n & 63;
                const int bb = m >> 11;
                const int sq = m & (SEQ - 1);
                const int m2 = m + 8;
                const int bb2 = m2 >> 11;
                const int sq2 = m2 & (SEQ - 1);
                float2 lo = make_float2(__uint_as_float(f2tf(v0)), __uint_as_float(f2tf(v1)));
                float2 hi = make_float2(__uint_as_float(f2tf(v2)), __uint_as_float(f2tf(v3)));
                *(float2*)(Y + (((size_t)bb * NHEAD + h) * SEQ + sq) * DEPTH + d) = lo;
                *(float2*)(Y + (((size_t)bb2 * NHEAD + h) * SEQ + sq2) * DEPTH + d) = hi;
            } else {
                // MODE 2: K transposed [B,H,64,S]
                const int h = n >> 6;
                const int d = n & 63;
                const int bb = m >> 11;
                const int sq = m & (SEQ - 1);
                const int m2 = m + 8;
                const int bb2 = m2 >> 11;
                const int sq2 = m2 & (SEQ - 1);
                const size_t base = ((size_t)bb * NHEAD + h) * DEPTH * SEQ;
                const size_t base2 = ((size_t)bb2 * NHEAD + h) * DEPTH * SEQ;
                Y[base + (size_t)d * SEQ + sq]        = __uint_as_float(f2tf(v0));
                Y[base + (size_t)(d + 1) * SEQ + sq]  = __uint_as_float(f2tf(v1));
                Y[base2 + (size_t)d * SEQ + sq2]       = __uint_as_float(f2tf(v2));
                Y[base2 + (size_t)(d + 1) * SEQ + sq2] = __uint_as_float(f2tf(v3));
            }
        }
    }
}

__global__ __launch_bounds__(256) void qkv_proj_kernel(
    const float* __restrict__ q, const float* __restrict__ k, const float* __restrict__ v,
    const float* __restrict__ wq, const float* __restrict__ wk, const float* __restrict__ wv,
    const float* __restrict__ bq, const float* __restrict__ bk, const float* __restrict__ bv)
{
    if (blockIdx.z == 0)      gemm_tf32_body<1>(q, wq, bq, g_qh);
    else if (blockIdx.z == 1) gemm_tf32_body<2>(k, wk, bk, g_kh);
    else                      gemm_tf32_body<1>(v, wv, bv, g_vh);
}

__global__ __launch_bounds__(256) void out_proj_kernel(
    const float* __restrict__ wo, const float* __restrict__ bo, float* __restrict__ out)
{
    gemm_tf32_body<0>(g_att, wo, bo, out);
}

// ===========================================================================
// tf32 tensor-core flash attention, cp.async double-buffered.
// CTA: 128 q-rows x one (b,h). 128 threads = 4 warps; warp owns 32 q-rows
// (2 m-tiles of 16). kv-tiles of 64, 32 iterations.
// K arrives pre-transposed [d][s] and pre-rounded -> straight cp.async copy.
// PV uses the k-permutation trick: P's C-fragment is consumed directly as the
// A-fragment (pi(t)=2t, pi(t+4)=2t+1); V rows are stored sigma-permuted
// (sigma(k) = (k&7)>>1 | ((k&1)<<2) within each 8-block) so B-fragment reads
// hit the SAME conflict-free addresses as the unpermuted layout. Zero shuffles.
// Smem (words): Qs 128x68 | K0 64x72 | K1 | V0 64x72 | V1 = 27136 w = 108544 B
//   -> 2 CTAs/SM.
// ===========================================================================
#define QSTR 68
#define KSTR 72
#define KVWORDS (64 * KSTR)  // 4608
#define FLASH_SMEM ((128 * QSTR + 4 * KVWORDS) * 4)   // 108544

__global__ __launch_bounds__(128, 2) void flash_attn_tf32_kernel(const float* __restrict__ mask)
{
    extern __shared__ uint32_t su[];
    uint32_t* Qs = su;                                   // [128][68]
    uint32_t* Kb0 = su + 128 * QSTR;                     // [64][72]  [d][kv]
    uint32_t* Kb1 = Kb0 + KVWORDS;
    uint32_t* Vb0 = Kb1 + KVWORDS;                       // [64][72]  [kv][d], rows sigma-permuted
    uint32_t* Vb1 = Vb0 + KVWORDS;

    const int bh = blockIdx.y;               // b*16 + h
    const int q0 = blockIdx.x * 128;
    const float* Qp = g_qh + ((size_t)bh * SEQ + q0) * DEPTH;
    const float* KpT = g_kh + (size_t)bh * DEPTH * SEQ;   // transposed [64][SEQ]
    const float* Vp = g_vh + (size_t)bh * SEQ * DEPTH;

    const int tid = threadIdx.x;
    const int lane = tid & 31;
    const int wid = tid >> 5;                // 0..3
    const int g = lane >> 2;                 // 0..7
    const int t = lane & 3;                  // 0..3
    const int wbase = wid * 32;              // warp's q-row base (local)

    // staging helpers: rows r0 + 8i, r0 in 0..7 -> sigma row for V stores
    const int r0 = tid >> 4;                 // 0..7
    const int c0 = (tid & 15) * 4;           // 0..60
    const int vr0 = (r0 >> 1) | ((r0 & 1) << 2);  // sigma(r0)

    // ---- prologue: stage Q + tile0, tile1 ----
    {
#pragma unroll
        for (int i = 0; i < 16; ++i) {
            const int r = r0 + i * 8;
            CP16(s2u(Qs + r * QSTR + c0), Qp + (size_t)r * DEPTH + c0);
        }
#pragma unroll
        for (int i = 0; i < 8; ++i) {
            const int r = r0 + i * 8;
            const int vr = vr0 + i * 8;
            CP16(s2u(Kb0 + r * KSTR + c0), KpT + (size_t)r * SEQ + 0 + c0);
            CP16(s2u(Vb0 + vr * KSTR + c0), Vp + (size_t)(0 + r) * DEPTH + c0);
        }
        CPCOMMIT();
#pragma unroll
        for (int i = 0; i < 8; ++i) {
            const int r = r0 + i * 8;
            const int vr = vr0 + i * 8;
            CP16(s2u(Kb1 + r * KSTR + c0), KpT + (size_t)r * SEQ + 64 + c0);
            CP16(s2u(Vb1 + vr * KSTR + c0), Vp + (size_t)(64 + r) * DEPTH + c0);
        }
        CPCOMMIT();
    }

    float m_i[4], l_i[4];
#pragma unroll
    for (int i = 0; i < 4; ++i) { m_i[i] = -1e30f; l_i[i] = 0.f; }
    float o[2][8][4];
#pragma unroll
    for (int mt = 0; mt < 2; ++mt)
#pragma unroll
        for (int nt = 0; nt < 8; ++nt)
#pragma unroll
            for (int r = 0; r < 4; ++r) o[mt][nt][r] = 0.f;

    const int NT = SEQ / 64;  // 32
    for (int kt = 0; kt < NT; ++kt) {
        const int k0g = kt * 64;
        CPWAIT1();
        __syncthreads();   // tile kt resident; prior readers of this buf done

        const uint32_t* Ks = (kt & 1) ? Kb1 : Kb0;
        const uint32_t* Vs = (kt & 1) ? Vb1 : Vb0;

        // ---- mask prefetch (issued before MMAs, consumed in softmax) ----
        float2 mk[2][8][2];
#pragma unroll
        for (int mt = 0; mt < 2; ++mt) {
            const float* mrA = mask + (size_t)(q0 + wbase + mt * 16 + g) * SEQ + k0g + 2 * t;
            const float* mrB = mrA + (size_t)8 * SEQ;
#pragma unroll
            for (int nt = 0; nt < 8; ++nt) {
                mk[mt][nt][0] = *(const float2*)(mrA + nt * 8);
                mk[mt][nt][1] = *(const float2*)(mrB + nt * 8);
            }
        }

        // ---- S = Q K^T ----
        float s[2][8][4];
#pragma unroll
        for (int mt = 0; mt < 2; ++mt)
#pragma unroll
            for (int nt = 0; nt < 8; ++nt)
#pragma unroll
                for (int r = 0; r < 4; ++r) s[mt][nt][r] = 0.f;

#pragma unroll
        for (int ks = 0; ks < 8; ++ks) {
            const int k0 = ks * 8;
            uint32_t a[2][4];
#pragma unroll
            for (int mt = 0; mt < 2; ++mt) {
                const uint32_t* base = Qs + (wbase + mt * 16 + g) * QSTR + k0 + t;
                a[mt][0] = base[0];
                a[mt][1] = base[8 * QSTR];
                a[mt][2] = base[4];
                a[mt][3] = base[8 * QSTR + 4];
            }
#pragma unroll
            for (int nt = 0; nt < 8; ++nt) {
                const uint32_t* bp = Ks + (k0 + t) * KSTR + nt * 8 + g;
                const uint32_t b0 = bp[0];
                const uint32_t b1 = bp[4 * KSTR];
                mma_tf32(s[0][nt][0], s[0][nt][1], s[0][nt][2], s[0][nt][3],
                         a[0][0], a[0][1], a[0][2], a[0][3], b0, b1);
                mma_tf32(s[1][nt][0], s[1][nt][1], s[1][nt][2], s[1][nt][3],
                         a[1][0], a[1][1], a[1][2], a[1][3], b0, b1);
            }
        }

        // ---- online softmax (per thread: 4 rows, 16 cols each) ----
        const float scale = 0.125f;
#pragma unroll
        for (int mt = 0; mt < 2; ++mt) {
            float mxA = -1e30f, mxB = -1e30f;
#pragma unroll
            for (int nt = 0; nt < 8; ++nt) {
                s[mt][nt][0] = s[mt][nt][0] * scale - 1e9f * mk[mt][nt][0].x;
                s[mt][nt][1] = s[mt][nt][1] * scale - 1e9f * mk[mt][nt][0].y;
                s[mt][nt][2] = s[mt][nt][2] * scale - 1e9f * mk[mt][nt][1].x;
                s[mt][nt][3] = s[mt][nt][3] * scale - 1e9f * mk[mt][nt][1].y;
                mxA = fmaxf(mxA, fmaxf(s[mt][nt][0], s[mt][nt][1]));
                mxB = fmaxf(mxB, fmaxf(s[mt][nt][2], s[mt][nt][3]));
            }
            mxA = fmaxf(mxA, __shfl_xor_sync(0xffffffffu, mxA, 1));
            mxA = fmaxf(mxA, __shfl_xor_sync(0xffffffffu, mxA, 2));
            mxB = fmaxf(mxB, __shfl_xor_sync(0xffffffffu, mxB, 1));
            mxB = fmaxf(mxB, __shfl_xor_sync(0xffffffffu, mxB, 2));

            const float mnA = fmaxf(m_i[2 * mt + 0], mxA);
            const float mnB = fmaxf(m_i[2 * mt + 1], mxB);
            const float corrA = __expf(m_i[2 * mt + 0] - mnA);
            const float corrB = __expf(m_i[2 * mt + 1] - mnB);
            m_i[2 * mt + 0] = mnA;
            m_i[2 * mt + 1] = mnB;

            float rsA = 0.f, rsB = 0.f;
#pragma unroll
            for (int nt = 0; nt < 8; ++nt) {
                s[mt][nt][0] = __expf(s[mt][nt][0] - mnA);
                s[mt][nt][1] = __expf(s[mt][nt][1] - mnA);
                s[mt][nt][2] = __expf(s[mt][nt][2] - mnB);
                s[mt][nt][3] = __expf(s[mt][nt][3] - mnB);
                rsA += s[mt][nt][0] + s[mt][nt][1];
                rsB += s[mt][nt][2] + s[mt][nt][3];
            }
            rsA += __shfl_xor_sync(0xffffffffu, rsA, 1);
            rsA += __shfl_xor_sync(0xffffffffu, rsA, 2);
            rsB += __shfl_xor_sync(0xffffffffu, rsB, 1);
            rsB += __shfl_xor_sync(0xffffffffu, rsB, 2);

            l_i[2 * mt + 0] = l_i[2 * mt + 0] * corrA + rsA;
            l_i[2 * mt + 1] = l_i[2 * mt + 1] * corrB + rsB;
#pragma unroll
            for (int nt = 0; nt < 8; ++nt) {
                o[mt][nt][0] *= corrA;
                o[mt][nt][1] *= corrA;
                o[mt][nt][2] *= corrB;
                o[mt][nt][3] *= corrB;
            }
        }

        // ---- O += P V, k-permuted: C-frag IS the A-frag (no shuffles) ----
        // a0 = P[g][pi(t)]   = c0   (pi(t)   = 2t)
        // a1 = P[g+8][pi(t)] = c2
        // a2 = P[g][pi(t+4)] = c1   (pi(t+4) = 2t+1)
        // a3 = P[g+8][pi(t+4)] = c3
        // V stored sigma-permuted so b0/b1 read rows k0+t / k0+t+4 (conflict-free).
#pragma unroll
        for (int ks = 0; ks < 8; ++ks) {
            const int k0 = ks * 8;
            uint32_t a[2][4];
#pragma unroll
            for (int mt = 0; mt < 2; ++mt) {
                a[mt][0] = f2tf(s[mt][ks][0]);
                a[mt][1] = f2tf(s[mt][ks][2]);
                a[mt][2] = f2tf(s[mt][ks][1]);
                a[mt][3] = f2tf(s[mt][ks][3]);
            }
#pragma unroll
            for (int nt = 0; nt < 8; ++nt) {
                const uint32_t* bp = Vs + (k0 + t) * KSTR + nt * 8 + g;
                const uint32_t b0 = bp[0];
                const uint32_t b1 = bp[4 * KSTR];
                mma_tf32(o[0][nt][0], o[0][nt][1], o[0][nt][2], o[0][nt][3],
                         a[0][0], a[0][1], a[0][2], a[0][3], b0, b1);
                mma_tf32(o[1][nt][0], o[1][nt][1], o[1][nt][2], o[1][nt][3],
                         a[1][0], a[1][1], a[1][2], a[1][3], b0, b1);
            }
        }

        __syncthreads();   // all warps done reading buf (kt&1) before refill

        // ---- stage tile kt+2 into buf (kt&1) ----
        if (kt + 2 < NT) {
            const int k2 = (kt + 2) * 64;
            uint32_t* Kd = (kt & 1) ? Kb1 : Kb0;
            uint32_t* Vd = (kt & 1) ? Vb1 : Vb0;
#pragma unroll
            for (int i = 0; i < 8; ++i) {
                const int r = r0 + i * 8;
                const int vr = vr0 + i * 8;
                CP16(s2u(Kd + r * KSTR + c0), KpT + (size_t)r * SEQ + k2 + c0);
                CP16(s2u(Vd + vr * KSTR + c0), Vp + (size_t)(k2 + r) * DEPTH + c0);
            }
        }
        CPCOMMIT();   // always commit (possibly empty) to keep wait accounting
    }

    // ---- epilogue: normalize + write merged-head layout [B,S,1024] ----
    const int bb2 = bh >> 4;
    const int h = bh & 15;
#pragma unroll
    for (int mt = 0; mt < 2; ++mt) {
        const float invA = 1.f / l_i[2 * mt + 0];
        const float invB = 1.f / l_i[2 * mt + 1];
        const int rowA = q0 + wbase + mt * 16 + g;
        float* oA = g_att + ((size_t)bb2 * SEQ + rowA) * D_MODEL + h * DEPTH + 2 * t;
        float* oB = oA + (size_t)8 * D_MODEL;
#pragma unroll
        for (int nt = 0; nt < 8; ++nt) {
            *(float2*)(oA + nt * 8) = make_float2(o[mt][nt][0] * invA, o[mt][nt][1] * invA);
            *(float2*)(oB + nt * 8) = make_float2(o[mt][nt][2] * invB, o[mt][nt][3] * invB);
        }
    }
}

// ---------------------------------------------------------------------------
extern "C" void kernel_launch(void* const* d_in, const int* in_sizes, int n_in,
                              void* d_out, int out_size)
{
    const float* q    = (const float*)d_in[0];
    const float* k    = (const float*)d_in[1];
    const float* v    = (const float*)d_in[2];
    const float* mask = (const float*)d_in[3];
    const float* wq   = (const float*)d_in[4];
    const float* bq   = (const float*)d_in[5];
    const float* wk   = (const float*)d_in[6];
    const float* bk   = (const float*)d_in[7];
    const float* wv   = (const float*)d_in[8];
    const float* bv   = (const float*)d_in[9];
    const float* wo   = (const float*)d_in[10];
    const float* bo   = (const float*)d_in[11];
    float* out = (float*)d_out;

    (void)in_sizes; (void)n_in; (void)out_size;

    cudaFuncSetAttribute(qkv_proj_kernel,
                         cudaFuncAttributeMaxDynamicSharedMemorySize, GEMM_SMEM);
    cudaFuncSetAttribute(out_proj_kernel,
                         cudaFuncAttributeMaxDynamicSharedMemorySize, GEMM_SMEM);
    cudaFuncSetAttribute(flash_attn_tf32_kernel,
                         cudaFuncAttributeMaxDynamicSharedMemorySize, FLASH_SMEM);

    dim3 gproj(D_MODEL / 128, MTOT / 128, 3);
    qkv_proj_kernel<<<gproj, 256, GEMM_SMEM>>>(q, k, v, wq, wk, wv, bq, bk, bv);

    flash_attn_tf32_kernel<<<dim3(SEQ / 128, BB * NHEAD), 128, FLASH_SMEM>>>(mask);

    out_proj_kernel<<<dim3(D_MODEL / 128, MTOT / 128), 256, GEMM_SMEM>>>(wo, bo, out);
}